// round 7
// baseline (speedup 1.0000x reference)
#include <cuda_runtime.h>
#include <cuda_bf16.h>
#include <math.h>

#define NN 100000
#define NE 20000
#define NP 3200000
#define D  512
#define NREP 4                    // edge accumulator replicas

// ---------------- scratch (device globals; no allocation) ----------------
__device__ float4 g_m[NN];            // gelu(x @ Wmsg^T)         [N,4]
__device__ float4 g_u[NN];            // x @ Wupd^T + b           [N,4]
__device__ float4 g_ef[NE];           // edge means

// zero-initialized accumulators, packed so ONE memset clears them all (3.6MB)
struct Scratch {
    float4 esum[NREP * NE];           // 1.28 MB
    float  ecnt[NREP * NE];           // 0.32 MB
    float4 nsum[NN];                  // 1.6 MB
    float  ncnt[NN];                  // 0.4 MB
};
__device__ Scratch g_s;

__device__ __forceinline__ float gelu_exact(float v) {
    return 0.5f * v * (1.0f + erff(v * 0.70710678118654752f));
}

// ---------------- packed f32x2 helpers (sm_100a) ----------------
__device__ __forceinline__ unsigned long long pk2(float a, float b) {
    unsigned long long r;
    asm("mov.b64 %0, {%1, %2};" : "=l"(r) : "f"(a), "f"(b));
    return r;
}
__device__ __forceinline__ void fma2(unsigned long long& d,
                                     unsigned long long a,
                                     unsigned long long b) {
    asm("fma.rn.f32x2 %0, %1, %2, %0;" : "+l"(d) : "l"(a), "l"(b));
}
__device__ __forceinline__ float upk_sum(unsigned long long v) {
    float x, y;
    asm("mov.b64 {%0, %1}, %2;" : "=f"(x), "=f"(y) : "l"(v));
    return x + y;
}

// ---- shared GEMV core: one warp computes 4 rows x 4 features ----
// acc[r][k] returned fully reduced (same value in all lanes).
__device__ __forceinline__ void gemv4x4(
    const float4* __restrict__ x4, const float4* sW,
    int row0, int lane, float acc[4][4])
{
    unsigned long long acc2[4][4];
    #pragma unroll
    for (int r = 0; r < 4; r++)
        #pragma unroll
        for (int k = 0; k < 4; k++) acc2[r][k] = 0ull;

    #pragma unroll
    for (int i = 0; i < 4; i++) {
        int c = i * 32 + lane;
        unsigned long long wlo[4], whi[4];
        #pragma unroll
        for (int k = 0; k < 4; k++) {
            float4 wv = sW[k * 128 + c];
            wlo[k] = pk2(wv.x, wv.y);
            whi[k] = pk2(wv.z, wv.w);
        }
        #pragma unroll
        for (int r = 0; r < 4; r++) {
            float4 xv = x4[(size_t)(row0 + r) * 128 + c];
            unsigned long long xlo = pk2(xv.x, xv.y);
            unsigned long long xhi = pk2(xv.z, xv.w);
            #pragma unroll
            for (int k = 0; k < 4; k++) {
                fma2(acc2[r][k], xlo, wlo[k]);
                fma2(acc2[r][k], xhi, whi[k]);
            }
        }
    }
    #pragma unroll
    for (int r = 0; r < 4; r++)
        #pragma unroll
        for (int k = 0; k < 4; k++) {
            float s = upk_sum(acc2[r][k]);
            #pragma unroll
            for (int off = 16; off > 0; off >>= 1)
                s += __shfl_xor_sync(0xFFFFFFFFu, s, off);
            acc[r][k] = s;
        }
}

// ---------------- kernel 1: msg-GEMV + GELU + pair counting ----------------
// 3125 blocks x 256 threads; warp = 4 rows x 4 msg features (32 rows/block).
// Phase B: each thread handles EXACTLY one int4 pair chunk (3125*256 = NP/4),
// so the count atomics spread evenly across the whole DRAM-bound kernel.
__global__ __launch_bounds__(256) void k_linear_m(
    const float4* __restrict__ x4,
    const float4* __restrict__ wmsg4,
    const int4*   __restrict__ pn4,
    const int4*   __restrict__ pe4)
{
    __shared__ float4 sW[4 * 128];
    int t = threadIdx.x;
    for (int i = t; i < 4 * 128; i += 256) sW[i] = wmsg4[i];
    __syncthreads();

    int warp = t >> 5, lane = t & 31;
    int row0 = (blockIdx.x * 8 + warp) * 4;

    float acc[4][4];
    gemv4x4(x4, sW, row0, lane, acc);

    if (lane < 4) {
        float4 mv;
        mv.x = gelu_exact(acc[lane][0]);
        mv.y = gelu_exact(acc[lane][1]);
        mv.z = gelu_exact(acc[lane][2]);
        mv.w = gelu_exact(acc[lane][3]);
        g_m[row0 + lane] = mv;
    }

    // ---- Phase B: multiplicity counts (index-only; overlaps GEMV) ----
    int tid = blockIdx.x * 256 + t;           // exactly NP/4 threads
    int4 n4 = __ldg(&pn4[tid]);
    int4 e4 = __ldg(&pe4[tid]);
    int erep = (t & (NREP - 1)) * NE;
    #pragma unroll
    for (int j = 0; j < 4; j++) {
        int n = (j == 0) ? n4.x : (j == 1) ? n4.y : (j == 2) ? n4.z : n4.w;
        int e = (j == 0) ? e4.x : (j == 1) ? e4.y : (j == 2) ? e4.z : e4.w;
        atomicAdd(&g_s.ecnt[erep + e], 1.0f);
        atomicAdd(&g_s.ncnt[n], 1.0f);
    }
}

// ---------------- kernel 2: upd-GEMV fused with edge scatter ----------------
// Same grid (3125 x 256). GEMV phase is DRAM-bound, scatter phase is
// L2-atomic-bound — fusing them overlaps the two disjoint resources.
// Block parity swaps phase order so concurrent CTAs mix both resource types.
__global__ __launch_bounds__(256) void k_fused_edges(
    const float4* __restrict__ x4,
    const float4* __restrict__ wupd4,
    const float*  __restrict__ b_upd,
    const int4*   __restrict__ pn4,
    const int4*   __restrict__ pe4)
{
    __shared__ float4 sW[4 * 128];
    __shared__ float  sB[4];
    int t = threadIdx.x;
    for (int i = t; i < 4 * 128; i += 256) sW[i] = wupd4[i];
    if (t < 4) sB[t] = b_upd[t];
    __syncthreads();

    int warp = t >> 5, lane = t & 31;
    int row0 = (blockIdx.x * 8 + warp) * 4;
    bool scatter_first = (blockIdx.x & 1);

    for (int phase = 0; phase < 2; phase++) {
        if ((phase == 0) == scatter_first) {
            // ---- edge scatter: one int4 chunk per thread ----
            int tid = blockIdx.x * 256 + t;
            int4 n4 = __ldg(&pn4[tid]);
            int4 e4 = __ldg(&pe4[tid]);
            int erep = (t & (NREP - 1)) * NE;
            #pragma unroll
            for (int j = 0; j < 4; j++) {
                int n = (j == 0) ? n4.x : (j == 1) ? n4.y : (j == 2) ? n4.z : n4.w;
                int e = (j == 0) ? e4.x : (j == 1) ? e4.y : (j == 2) ? e4.z : e4.w;
                float4 mv = g_m[n];
                atomicAdd(&g_s.esum[erep + e], mv);   // RED.128
            }
        } else {
            // ---- upd-GEMV ----
            float acc[4][4];
            gemv4x4(x4, sW, row0, lane, acc);
            if (lane < 4) {
                float4 uv;
                uv.x = acc[lane][0] + sB[0];
                uv.y = acc[lane][1] + sB[1];
                uv.z = acc[lane][2] + sB[2];
                uv.w = acc[lane][3] + sB[3];
                g_u[row0 + lane] = uv;
            }
        }
    }
}

// ---------------- kernel 3: edge mean (sum replicas) ----------------
__global__ void k_edge_mean() {
    int e = blockIdx.x * blockDim.x + threadIdx.x;
    if (e >= NE) return;
    float4 s = make_float4(0.f, 0.f, 0.f, 0.f);
    float cnt = 0.0f;
    #pragma unroll
    for (int r = 0; r < NREP; r++) {
        float4 v = g_s.esum[r * NE + e];
        s.x += v.x; s.y += v.y; s.z += v.z; s.w += v.w;
        cnt += g_s.ecnt[r * NE + e];
    }
    float inv = 1.0f / fmaxf(cnt, 1.0f);
    g_ef[e] = make_float4(s.x * inv, s.y * inv, s.z * inv, s.w * inv);
}

// ---------------- kernel 4: pair scatter #2 (edge means -> node sums) ----------------
__global__ __launch_bounds__(256) void k_scatter_nodes(
    const int4* __restrict__ pn4,
    const int4* __restrict__ pe4)
{
    int t = blockIdx.x * blockDim.x + threadIdx.x;
    if (t >= NP / 4) return;
    int4 n4 = __ldg(&pn4[t]);
    int4 e4 = __ldg(&pe4[t]);

    #pragma unroll
    for (int j = 0; j < 4; j++) {
        int n = (j == 0) ? n4.x : (j == 1) ? n4.y : (j == 2) ? n4.z : n4.w;
        int e = (j == 0) ? e4.x : (j == 1) ? e4.y : (j == 2) ? e4.z : e4.w;
        float4 ev = g_ef[e];
        atomicAdd(&g_s.nsum[n], ev);          // RED.128 (only atomic here)
    }
}

// ---------------- kernel 5: update + log_softmax ----------------
__global__ void k_final(float4* __restrict__ out4) {
    int i = blockIdx.x * blockDim.x + threadIdx.x;
    if (i >= NN) return;
    float4 u = g_u[i];
    float4 s = g_s.nsum[i];
    float inv = 1.0f / fmaxf(g_s.ncnt[i], 1.0f);
    float h0 = gelu_exact(u.x + s.x * inv);
    float h1 = gelu_exact(u.y + s.y * inv);
    float h2 = gelu_exact(u.z + s.z * inv);
    float h3 = gelu_exact(u.w + s.w * inv);
    float mx = fmaxf(fmaxf(h0, h1), fmaxf(h2, h3));
    float lse = mx + logf(expf(h0 - mx) + expf(h1 - mx)
                        + expf(h2 - mx) + expf(h3 - mx));
    out4[i] = make_float4(h0 - lse, h1 - lse, h2 - lse, h3 - lse);
}

// ---------------- launch ----------------
extern "C" void kernel_launch(void* const* d_in, const int* in_sizes, int n_in,
                              void* d_out, int out_size) {
    const float* x         = (const float*)d_in[0];
    const int*   pair_node = (const int*)d_in[1];
    const int*   pair_edge = (const int*)d_in[2];
    const float* W_msg     = (const float*)d_in[3];
    const float* W_upd     = (const float*)d_in[4];
    const float* b_upd     = (const float*)d_in[5];
    float4* out4 = (float4*)d_out;

    // symbol lookup hoisted out of the capture path (host query, done once)
    static void* scratch_ptr = nullptr;
    if (!scratch_ptr) cudaGetSymbolAddress(&scratch_ptr, g_s);
    cudaMemsetAsync(scratch_ptr, 0, sizeof(Scratch));

    k_linear_m<<<NN / 32, 256>>>((const float4*)x,
                                 (const float4*)W_msg,
                                 (const int4*)pair_node,
                                 (const int4*)pair_edge);

    k_fused_edges<<<NN / 32, 256>>>((const float4*)x,
                                    (const float4*)W_upd,
                                    b_upd,
                                    (const int4*)pair_node,
                                    (const int4*)pair_edge);

    k_edge_mean<<<(NE + 255) / 256, 256>>>();

    k_scatter_nodes<<<(NP / 4 + 255) / 256, 256>>>((const int4*)pair_node,
                                                   (const int4*)pair_edge);

    k_final<<<(NN + 255) / 256, 256>>>(out4);
}

// round 8
// speedup vs baseline: 1.0628x; 1.0628x over previous
#include <cuda_runtime.h>
#include <cuda_bf16.h>
#include <math.h>

#define NN 100000
#define NE 20000
#define NP 3200000
#define D  512
#define NREP 4                    // edge accumulator replicas

// split point for node rows (multiple of 16)
#define ROWS_A      50048         // kernel A computes rows [0, ROWS_A)
#define A_GEMV_CTAS 3128          // 3128 * 16 = 50048
#define A_CNT_CTAS  782           // 3910 = 5 * 782
#define A_GRID      3910
#define B_GEMV_CTAS 3122          // 3122 * 16 = 49952 rows [50048, 100000)
#define B_SC_CTAS   781           // 3905 = 5 * 781
#define B_GRID      3905
#define NCHUNK      (NP / 4)      // 800000 int4 pair chunks

// ---------------- scratch (device globals; no allocation) ----------------
__device__ float4 g_m[NN];            // gelu(x @ Wmsg^T)         [N,4]
__device__ float4 g_u[NN];            // x @ Wupd^T + b           [N,4]
__device__ float4 g_ef[NE];           // edge means

// zero-initialized accumulators, packed so ONE memset clears them all (3.6MB)
struct Scratch {
    float4 esum[NREP * NE];           // 1.28 MB
    float  ecnt[NREP * NE];           // 0.32 MB
    float4 nsum[NN];                  // 1.6 MB
    float  ncnt[NN];                  // 0.4 MB
};
__device__ Scratch g_s;

__device__ __forceinline__ float gelu_exact(float v) {
    return 0.5f * v * (1.0f + erff(v * 0.70710678118654752f));
}

// ---------------- packed f32x2 helpers (sm_100a) ----------------
__device__ __forceinline__ unsigned long long pk2(float a, float b) {
    unsigned long long r;
    asm("mov.b64 %0, {%1, %2};" : "=l"(r) : "f"(a), "f"(b));
    return r;
}
__device__ __forceinline__ void fma2(unsigned long long& d,
                                     unsigned long long a,
                                     unsigned long long b) {
    asm("fma.rn.f32x2 %0, %1, %2, %0;" : "+l"(d) : "l"(a), "l"(b));
}
__device__ __forceinline__ float upk_sum(unsigned long long v) {
    float x, y;
    asm("mov.b64 {%0, %1}, %2;" : "=f"(x), "=f"(y) : "l"(v));
    return x + y;
}

// ---- dual GEMV core: one warp computes 2 rows x 8 features (R5-proven) ----
// sW holds Wmsg rows 0-3 then Wupd rows 4-7. Writes g_m and g_u for 2 rows.
__device__ __forceinline__ void dual_gemv_2rows(
    const float4* __restrict__ x4, const float4* sW, const float* sB,
    int row0, int lane)
{
    unsigned long long acc2[2][8];
    #pragma unroll
    for (int r = 0; r < 2; r++)
        #pragma unroll
        for (int k = 0; k < 8; k++) acc2[r][k] = 0ull;

    #pragma unroll
    for (int i = 0; i < 4; i++) {
        int c = i * 32 + lane;
        unsigned long long wlo[8], whi[8];
        #pragma unroll
        for (int k = 0; k < 8; k++) {
            float4 wv = sW[k * 128 + c];
            wlo[k] = pk2(wv.x, wv.y);
            whi[k] = pk2(wv.z, wv.w);
        }
        #pragma unroll
        for (int r = 0; r < 2; r++) {
            float4 xv = x4[(size_t)(row0 + r) * 128 + c];
            unsigned long long xlo = pk2(xv.x, xv.y);
            unsigned long long xhi = pk2(xv.z, xv.w);
            #pragma unroll
            for (int k = 0; k < 8; k++) {
                fma2(acc2[r][k], xlo, wlo[k]);
                fma2(acc2[r][k], xhi, whi[k]);
            }
        }
    }

    float acc[2][8];
    #pragma unroll
    for (int r = 0; r < 2; r++)
        #pragma unroll
        for (int k = 0; k < 8; k++) {
            float s = upk_sum(acc2[r][k]);
            #pragma unroll
            for (int off = 16; off > 0; off >>= 1)
                s += __shfl_xor_sync(0xFFFFFFFFu, s, off);
            acc[r][k] = s;
        }

    if (lane < 2) {
        int row = row0 + lane;
        float4 mv;
        mv.x = gelu_exact(acc[lane][0]);
        mv.y = gelu_exact(acc[lane][1]);
        mv.z = gelu_exact(acc[lane][2]);
        mv.w = gelu_exact(acc[lane][3]);
        g_m[row] = mv;
        float4 uv;
        uv.x = acc[lane][4] + sB[0];
        uv.y = acc[lane][5] + sB[1];
        uv.z = acc[lane][6] + sB[2];
        uv.w = acc[lane][7] + sB[3];
        g_u[row] = uv;
    }
}

// ---------------- kernel A: GEMV rows [0,ROWS_A) || dedicated count CTAs ----------------
// Role by bid%5: 4-of-5 CTAs = GEMV (DRAM-bound), 1-of-5 = counts (L2-atomic-bound).
// Roles interleave across the launch order so every wave mixes both resources.
__global__ __launch_bounds__(256) void k_A(
    const float4* __restrict__ x4,
    const float4* __restrict__ wmsg4,
    const float4* __restrict__ wupd4,
    const float*  __restrict__ b_upd,
    const int4*   __restrict__ pn4,
    const int4*   __restrict__ pe4)
{
    __shared__ float4 sW[8 * 128];
    __shared__ float  sB[4];
    int bid = blockIdx.x;
    int t = threadIdx.x;
    int r5 = bid % 5;
    int g  = bid / 5;

    if (r5 == 4) {
        // ---- count CTA: all pair multiplicity counts (ecnt, ncnt) ----
        int erep = (t & (NREP - 1)) * NE;
        for (int idx = g * 256 + t; idx < NCHUNK; idx += A_CNT_CTAS * 256) {
            int4 n4 = __ldg(&pn4[idx]);
            int4 e4 = __ldg(&pe4[idx]);
            #pragma unroll
            for (int j = 0; j < 4; j++) {
                int n = (j == 0) ? n4.x : (j == 1) ? n4.y : (j == 2) ? n4.z : n4.w;
                int e = (j == 0) ? e4.x : (j == 1) ? e4.y : (j == 2) ? e4.z : e4.w;
                atomicAdd(&g_s.ecnt[erep + e], 1.0f);
                atomicAdd(&g_s.ncnt[n], 1.0f);
            }
        }
        return;
    }

    // ---- GEMV CTA ----
    for (int i = t; i < 4 * 128; i += 256) sW[i] = wmsg4[i];
    for (int i = t; i < 4 * 128; i += 256) sW[4 * 128 + i] = wupd4[i];
    if (t < 4) sB[t] = b_upd[t];
    __syncthreads();

    int gemv_idx = g * 4 + r5;                 // [0, 3128)
    int warp = t >> 5, lane = t & 31;
    int row0 = (gemv_idx * 8 + warp) * 2;      // rows [0, 50048)
    dual_gemv_2rows(x4, sW, sB, row0, lane);
}

// ---------------- kernel B: GEMV rows [ROWS_A,NN) || scatter pairs with n<ROWS_A ----------------
__global__ __launch_bounds__(256) void k_B(
    const float4* __restrict__ x4,
    const float4* __restrict__ wmsg4,
    const float4* __restrict__ wupd4,
    const float*  __restrict__ b_upd,
    const int4*   __restrict__ pn4,
    const int4*   __restrict__ pe4)
{
    __shared__ float4 sW[8 * 128];
    __shared__ float  sB[4];
    int bid = blockIdx.x;
    int t = threadIdx.x;
    int r5 = bid % 5;
    int g  = bid / 5;

    if (r5 == 4) {
        // ---- scatter CTA: esum for pairs whose node is in A's half ----
        int erep = (t & (NREP - 1)) * NE;
        for (int idx = g * 256 + t; idx < NCHUNK; idx += B_SC_CTAS * 256) {
            int4 n4 = __ldg(&pn4[idx]);
            int4 e4 = __ldg(&pe4[idx]);
            #pragma unroll
            for (int j = 0; j < 4; j++) {
                int n = (j == 0) ? n4.x : (j == 1) ? n4.y : (j == 2) ? n4.z : n4.w;
                int e = (j == 0) ? e4.x : (j == 1) ? e4.y : (j == 2) ? e4.z : e4.w;
                if (n < ROWS_A) {
                    float4 mv = g_m[n];
                    atomicAdd(&g_s.esum[erep + e], mv);   // RED.128
                }
            }
        }
        return;
    }

    // ---- GEMV CTA ----
    for (int i = t; i < 4 * 128; i += 256) sW[i] = wmsg4[i];
    for (int i = t; i < 4 * 128; i += 256) sW[4 * 128 + i] = wupd4[i];
    if (t < 4) sB[t] = b_upd[t];
    __syncthreads();

    int gemv_idx = g * 4 + r5;                 // [0, 3124); need [0, 3122)
    if (gemv_idx >= B_GEMV_CTAS) return;
    int warp = t >> 5, lane = t & 31;
    int row0 = ROWS_A + (gemv_idx * 8 + warp) * 2;  // rows [50048, 100000)
    dual_gemv_2rows(x4, sW, sB, row0, lane);
}

// ---------------- kernel C: scatter remaining pairs (n >= ROWS_A) ----------------
__global__ __launch_bounds__(256) void k_scatter_rest(
    const int4* __restrict__ pn4,
    const int4* __restrict__ pe4)
{
    int t = blockIdx.x * blockDim.x + threadIdx.x;
    if (t >= NCHUNK) return;
    int4 n4 = __ldg(&pn4[t]);
    int4 e4 = __ldg(&pe4[t]);
    int erep = (threadIdx.x & (NREP - 1)) * NE;

    #pragma unroll
    for (int j = 0; j < 4; j++) {
        int n = (j == 0) ? n4.x : (j == 1) ? n4.y : (j == 2) ? n4.z : n4.w;
        int e = (j == 0) ? e4.x : (j == 1) ? e4.y : (j == 2) ? e4.z : e4.w;
        if (n >= ROWS_A) {
            float4 mv = g_m[n];
            atomicAdd(&g_s.esum[erep + e], mv);          // RED.128
        }
    }
}

// ---------------- kernel: edge mean (sum replicas) ----------------
__global__ void k_edge_mean() {
    int e = blockIdx.x * blockDim.x + threadIdx.x;
    if (e >= NE) return;
    float4 s = make_float4(0.f, 0.f, 0.f, 0.f);
    float cnt = 0.0f;
    #pragma unroll
    for (int r = 0; r < NREP; r++) {
        float4 v = g_s.esum[r * NE + e];
        s.x += v.x; s.y += v.y; s.z += v.z; s.w += v.w;
        cnt += g_s.ecnt[r * NE + e];
    }
    float inv = 1.0f / fmaxf(cnt, 1.0f);
    g_ef[e] = make_float4(s.x * inv, s.y * inv, s.z * inv, s.w * inv);
}

// ---------------- kernel: pair scatter #2 (edge means -> node sums) ----------------
__global__ __launch_bounds__(256) void k_scatter_nodes(
    const int4* __restrict__ pn4,
    const int4* __restrict__ pe4)
{
    int t = blockIdx.x * blockDim.x + threadIdx.x;
    if (t >= NCHUNK) return;
    int4 n4 = __ldg(&pn4[t]);
    int4 e4 = __ldg(&pe4[t]);

    #pragma unroll
    for (int j = 0; j < 4; j++) {
        int n = (j == 0) ? n4.x : (j == 1) ? n4.y : (j == 2) ? n4.z : n4.w;
        int e = (j == 0) ? e4.x : (j == 1) ? e4.y : (j == 2) ? e4.z : e4.w;
        float4 ev = g_ef[e];
        atomicAdd(&g_s.nsum[n], ev);          // RED.128 (only atomic here)
    }
}

// ---------------- kernel: update + log_softmax ----------------
__global__ void k_final(float4* __restrict__ out4) {
    int i = blockIdx.x * blockDim.x + threadIdx.x;
    if (i >= NN) return;
    float4 u = g_u[i];
    float4 s = g_s.nsum[i];
    float inv = 1.0f / fmaxf(g_s.ncnt[i], 1.0f);
    float h0 = gelu_exact(u.x + s.x * inv);
    float h1 = gelu_exact(u.y + s.y * inv);
    float h2 = gelu_exact(u.z + s.z * inv);
    float h3 = gelu_exact(u.w + s.w * inv);
    float mx = fmaxf(fmaxf(h0, h1), fmaxf(h2, h3));
    float lse = mx + logf(expf(h0 - mx) + expf(h1 - mx)
                        + expf(h2 - mx) + expf(h3 - mx));
    out4[i] = make_float4(h0 - lse, h1 - lse, h2 - lse, h3 - lse);
}

// ---------------- launch ----------------
extern "C" void kernel_launch(void* const* d_in, const int* in_sizes, int n_in,
                              void* d_out, int out_size) {
    const float* x         = (const float*)d_in[0];
    const int*   pair_node = (const int*)d_in[1];
    const int*   pair_edge = (const int*)d_in[2];
    const float* W_msg     = (const float*)d_in[3];
    const float* W_upd     = (const float*)d_in[4];
    const float* b_upd     = (const float*)d_in[5];
    float4* out4 = (float4*)d_out;

    static void* scratch_ptr = nullptr;
    if (!scratch_ptr) cudaGetSymbolAddress(&scratch_ptr, g_s);
    cudaMemsetAsync(scratch_ptr, 0, sizeof(Scratch));

    k_A<<<A_GRID, 256>>>((const float4*)x,
                         (const float4*)W_msg, (const float4*)W_upd, b_upd,
                         (const int4*)pair_node, (const int4*)pair_edge);

    k_B<<<B_GRID, 256>>>((const float4*)x,
                         (const float4*)W_msg, (const float4*)W_upd, b_upd,
                         (const int4*)pair_node, (const int4*)pair_edge);

    k_scatter_rest<<<(NCHUNK + 255) / 256, 256>>>((const int4*)pair_node,
                                                  (const int4*)pair_edge);

    k_edge_mean<<<(NE + 255) / 256, 256>>>();

    k_scatter_nodes<<<(NCHUNK + 255) / 256, 256>>>((const int4*)pair_node,
                                                   (const int4*)pair_edge);

    k_final<<<(NN + 255) / 256, 256>>>(out4);
}

// round 9
// speedup vs baseline: 1.1952x; 1.1246x over previous
#include <cuda_runtime.h>
#include <cuda_bf16.h>
#include <math.h>

#define NN 100000
#define NE 20000
#define NP 3200000
#define D  512
#define NREP 4                    // edge accumulator replicas

// ---------------- scratch (device globals; no allocation) ----------------
__device__ float4 g_m[NN];            // gelu(x @ Wmsg^T)         [N,4]
__device__ float4 g_u[NN];            // x @ Wupd^T + b           [N,4]
__device__ float4 g_ef[NE];           // edge means

// zero-initialized accumulators, packed so ONE memset clears them all (3.6MB)
struct Scratch {
    float4 esum[NREP * NE];           // 1.28 MB
    float  ecnt[NREP * NE];           // 0.32 MB
    float4 nsum[NN];                  // 1.6 MB
    float  ncnt[NN];                  // 0.4 MB
};
__device__ Scratch g_s;

__device__ __forceinline__ float gelu_exact(float v) {
    return 0.5f * v * (1.0f + erff(v * 0.70710678118654752f));
}

// ---------------- packed f32x2 helpers (sm_100a) ----------------
__device__ __forceinline__ unsigned long long pk2(float a, float b) {
    unsigned long long r;
    asm("mov.b64 %0, {%1, %2};" : "=l"(r) : "f"(a), "f"(b));
    return r;
}
__device__ __forceinline__ void fma2(unsigned long long& d,
                                     unsigned long long a,
                                     unsigned long long b) {
    asm("fma.rn.f32x2 %0, %1, %2, %0;" : "+l"(d) : "l"(a), "l"(b));
}
__device__ __forceinline__ float upk_sum(unsigned long long v) {
    float x, y;
    asm("mov.b64 {%0, %1}, %2;" : "=f"(x), "=f"(y) : "l"(v));
    return x + y;
}

// ---------------- kernel 1: fused dual GEMV + GELU + balanced pair counting ----------------
// Phase A: each warp computes 2 rows x 8 features (Wmsg 0-3, Wupd 4-7);
//          W in smem (16KB), x read once coalesced float4.
// Phase B: EVERY thread (6250 blocks x 256 = 1.6M) counts exactly one int2
//          chunk (2 pairs) -> count atomics spread evenly across the whole
//          DRAM-bound kernel, hiding them in the L2-atomic slack.
__global__ __launch_bounds__(256) void k_linear(
    const float4* __restrict__ x4,      // [N, 128] float4
    const float4* __restrict__ wmsg4,   // [4, 128]
    const float4* __restrict__ wupd4,   // [4, 128]
    const float*  __restrict__ b_upd,   // [4]
    const int2*   __restrict__ pn2,
    const int2*   __restrict__ pe2)
{
    __shared__ float4 sW[8 * 128];
    __shared__ float  sB[4];

    int t = threadIdx.x;
    for (int i = t; i < 4 * 128; i += 256) sW[i] = wmsg4[i];
    for (int i = t; i < 4 * 128; i += 256) sW[4 * 128 + i] = wupd4[i];
    if (t < 4) sB[t] = b_upd[t];
    __syncthreads();

    int warp = t >> 5;
    int lane = t & 31;
    int row0 = (blockIdx.x * 8 + warp) * 2;   // 6250 blocks * 16 rows = 100000

    unsigned long long acc2[2][8];
    #pragma unroll
    for (int r = 0; r < 2; r++)
        #pragma unroll
        for (int k = 0; k < 8; k++) acc2[r][k] = 0ull;

    #pragma unroll
    for (int i = 0; i < 4; i++) {
        int c = i * 32 + lane;                // float4 column index 0..127
        unsigned long long wlo[8], whi[8];
        #pragma unroll
        for (int k = 0; k < 8; k++) {
            float4 wv = sW[k * 128 + c];
            wlo[k] = pk2(wv.x, wv.y);
            whi[k] = pk2(wv.z, wv.w);
        }
        #pragma unroll
        for (int r = 0; r < 2; r++) {
            float4 xv = x4[(size_t)(row0 + r) * 128 + c];
            unsigned long long xlo = pk2(xv.x, xv.y);
            unsigned long long xhi = pk2(xv.z, xv.w);
            #pragma unroll
            for (int k = 0; k < 8; k++) {
                fma2(acc2[r][k], xlo, wlo[k]);
                fma2(acc2[r][k], xhi, whi[k]);
            }
        }
    }

    // collapse packed halves, butterfly reduce across the warp
    float acc[2][8];
    #pragma unroll
    for (int r = 0; r < 2; r++)
        #pragma unroll
        for (int k = 0; k < 8; k++) {
            float s = upk_sum(acc2[r][k]);
            #pragma unroll
            for (int off = 16; off > 0; off >>= 1)
                s += __shfl_xor_sync(0xFFFFFFFFu, s, off);
            acc[r][k] = s;
        }

    if (lane < 2) {
        int row = row0 + lane;
        float4 mv;
        mv.x = gelu_exact(acc[lane][0]);
        mv.y = gelu_exact(acc[lane][1]);
        mv.z = gelu_exact(acc[lane][2]);
        mv.w = gelu_exact(acc[lane][3]);
        g_m[row] = mv;
        float4 uv;
        uv.x = acc[lane][4] + sB[0];
        uv.y = acc[lane][5] + sB[1];
        uv.z = acc[lane][6] + sB[2];
        uv.w = acc[lane][7] + sB[3];
        g_u[row] = uv;
    }

    // ---- Phase B: multiplicity counts, one int2 chunk per thread ----
    int tid = blockIdx.x * 256 + t;           // [0, 1.6M) == NP/2 chunks
    int2 n2 = __ldg(&pn2[tid]);
    int2 e2 = __ldg(&pe2[tid]);
    int erep = (t & (NREP - 1)) * NE;
    atomicAdd(&g_s.ecnt[erep + e2.x], 1.0f);
    atomicAdd(&g_s.ncnt[n2.x], 1.0f);
    atomicAdd(&g_s.ecnt[erep + e2.y], 1.0f);
    atomicAdd(&g_s.ncnt[n2.y], 1.0f);
}

// ---------------- kernel 2: pair scatter #1 (node msgs -> edge sums) ----------------
// Single RED.128 per pair; 4 pairs per thread via int4 index loads.
__global__ __launch_bounds__(256) void k_scatter_edges(
    const int4* __restrict__ pn4,
    const int4* __restrict__ pe4)
{
    int t = blockIdx.x * blockDim.x + threadIdx.x;
    if (t >= NP / 4) return;
    int4 n4 = __ldg(&pn4[t]);
    int4 e4 = __ldg(&pe4[t]);
    int erep = (threadIdx.x & (NREP - 1)) * NE;

    #pragma unroll
    for (int j = 0; j < 4; j++) {
        int n = (j == 0) ? n4.x : (j == 1) ? n4.y : (j == 2) ? n4.z : n4.w;
        int e = (j == 0) ? e4.x : (j == 1) ? e4.y : (j == 2) ? e4.z : e4.w;
        float4 mv = g_m[n];
        atomicAdd(&g_s.esum[erep + e], mv);      // RED.128 (only atomic here)
    }
}

// ---------------- kernel 3: edge mean (sum replicas) ----------------
__global__ void k_edge_mean() {
    int e = blockIdx.x * blockDim.x + threadIdx.x;
    if (e >= NE) return;
    float4 s = make_float4(0.f, 0.f, 0.f, 0.f);
    float cnt = 0.0f;
    #pragma unroll
    for (int r = 0; r < NREP; r++) {
        float4 v = g_s.esum[r * NE + e];
        s.x += v.x; s.y += v.y; s.z += v.z; s.w += v.w;
        cnt += g_s.ecnt[r * NE + e];
    }
    float inv = 1.0f / fmaxf(cnt, 1.0f);
    g_ef[e] = make_float4(s.x * inv, s.y * inv, s.z * inv, s.w * inv);
}

// ---------------- kernel 4: pair scatter #2 (edge means -> node sums) ----------------
__global__ __launch_bounds__(256) void k_scatter_nodes(
    const int4* __restrict__ pn4,
    const int4* __restrict__ pe4)
{
    int t = blockIdx.x * blockDim.x + threadIdx.x;
    if (t >= NP / 4) return;
    int4 n4 = __ldg(&pn4[t]);
    int4 e4 = __ldg(&pe4[t]);

    #pragma unroll
    for (int j = 0; j < 4; j++) {
        int n = (j == 0) ? n4.x : (j == 1) ? n4.y : (j == 2) ? n4.z : n4.w;
        int e = (j == 0) ? e4.x : (j == 1) ? e4.y : (j == 2) ? e4.z : e4.w;
        float4 ev = g_ef[e];
        atomicAdd(&g_s.nsum[n], ev);             // RED.128 (only atomic here)
    }
}

// ---------------- kernel 5: update + log_softmax ----------------
__global__ void k_final(float4* __restrict__ out4) {
    int i = blockIdx.x * blockDim.x + threadIdx.x;
    if (i >= NN) return;
    float4 u = g_u[i];
    float4 s = g_s.nsum[i];
    float inv = 1.0f / fmaxf(g_s.ncnt[i], 1.0f);
    float h0 = gelu_exact(u.x + s.x * inv);
    float h1 = gelu_exact(u.y + s.y * inv);
    float h2 = gelu_exact(u.z + s.z * inv);
    float h3 = gelu_exact(u.w + s.w * inv);
    float mx = fmaxf(fmaxf(h0, h1), fmaxf(h2, h3));
    float lse = mx + logf(expf(h0 - mx) + expf(h1 - mx)
                        + expf(h2 - mx) + expf(h3 - mx));
    out4[i] = make_float4(h0 - lse, h1 - lse, h2 - lse, h3 - lse);
}

// ---------------- launch ----------------
extern "C" void kernel_launch(void* const* d_in, const int* in_sizes, int n_in,
                              void* d_out, int out_size) {
    const float* x         = (const float*)d_in[0];
    const int*   pair_node = (const int*)d_in[1];
    const int*   pair_edge = (const int*)d_in[2];
    const float* W_msg     = (const float*)d_in[3];
    const float* W_upd     = (const float*)d_in[4];
    const float* b_upd     = (const float*)d_in[5];
    float4* out4 = (float4*)d_out;

    static void* scratch_ptr = nullptr;
    if (!scratch_ptr) cudaGetSymbolAddress(&scratch_ptr, g_s);
    cudaMemsetAsync(scratch_ptr, 0, sizeof(Scratch));

    k_linear<<<NN / 16, 256>>>((const float4*)x,
                               (const float4*)W_msg,
                               (const float4*)W_upd,
                               b_upd,
                               (const int2*)pair_node,
                               (const int2*)pair_edge);

    k_scatter_edges<<<(NP / 4 + 255) / 256, 256>>>((const int4*)pair_node,
                                                   (const int4*)pair_edge);

    k_edge_mean<<<(NE + 255) / 256, 256>>>();

    k_scatter_nodes<<<(NP / 4 + 255) / 256, 256>>>((const int4*)pair_node,
                                                   (const int4*)pair_edge);

    k_final<<<(NN + 255) / 256, 256>>>(out4);
}

// round 10
// speedup vs baseline: 1.2225x; 1.0228x over previous
#include <cuda_runtime.h>
#include <cuda_bf16.h>
#include <math.h>

#define NN 100000
#define NE 20000
#define NP 3200000
#define D  512
#define NREP 4                    // edge accumulator replicas

// ---------------- scratch (device globals; no allocation) ----------------
__device__ float4 g_m[NN];            // gelu(x @ Wmsg^T)         [N,4]
__device__ float4 g_u[NN];            // x @ Wupd^T + b           [N,4]
__device__ float4 g_ef[NE];           // edge means

// zero-initialized accumulators, packed so ONE memset clears them all (3.6MB)
struct Scratch {
    float4 esum[NREP * NE];           // 1.28 MB
    float  ecnt[NREP * NE];           // 0.32 MB
    float4 nsum[NN];                  // 1.6 MB
    float  ncnt[NN];                  // 0.4 MB
};
__device__ Scratch g_s;

__device__ __forceinline__ float gelu_exact(float v) {
    return 0.5f * v * (1.0f + erff(v * 0.70710678118654752f));
}

// ---------------- packed f32x2 helpers (sm_100a) ----------------
__device__ __forceinline__ unsigned long long pk2(float a, float b) {
    unsigned long long r;
    asm("mov.b64 %0, {%1, %2};" : "=l"(r) : "f"(a), "f"(b));
    return r;
}
__device__ __forceinline__ void fma2(unsigned long long& d,
                                     unsigned long long a,
                                     unsigned long long b) {
    asm("fma.rn.f32x2 %0, %1, %2, %0;" : "+l"(d) : "l"(a), "l"(b));
}
__device__ __forceinline__ float upk_sum(unsigned long long v) {
    float x, y;
    asm("mov.b64 {%0, %1}, %2;" : "=f"(x), "=f"(y) : "l"(v));
    return x + y;
}

// ---------------- kernel 1: fused dual GEMV + GELU + balanced pair counting ----------------
__global__ __launch_bounds__(256) void k_linear(
    const float4* __restrict__ x4,      // [N, 128] float4
    const float4* __restrict__ wmsg4,   // [4, 128]
    const float4* __restrict__ wupd4,   // [4, 128]
    const float*  __restrict__ b_upd,   // [4]
    const int2*   __restrict__ pn2,
    const int2*   __restrict__ pe2)
{
    __shared__ float4 sW[8 * 128];
    __shared__ float  sB[4];

    int t = threadIdx.x;
    for (int i = t; i < 4 * 128; i += 256) sW[i] = wmsg4[i];
    for (int i = t; i < 4 * 128; i += 256) sW[4 * 128 + i] = wupd4[i];
    if (t < 4) sB[t] = b_upd[t];
    __syncthreads();

    int warp = t >> 5;
    int lane = t & 31;
    int row0 = (blockIdx.x * 8 + warp) * 2;   // 6250 blocks * 16 rows = 100000

    unsigned long long acc2[2][8];
    #pragma unroll
    for (int r = 0; r < 2; r++)
        #pragma unroll
        for (int k = 0; k < 8; k++) acc2[r][k] = 0ull;

    #pragma unroll
    for (int i = 0; i < 4; i++) {
        int c = i * 32 + lane;                // float4 column index 0..127
        unsigned long long wlo[8], whi[8];
        #pragma unroll
        for (int k = 0; k < 8; k++) {
            float4 wv = sW[k * 128 + c];
            wlo[k] = pk2(wv.x, wv.y);
            whi[k] = pk2(wv.z, wv.w);
        }
        #pragma unroll
        for (int r = 0; r < 2; r++) {
            float4 xv = x4[(size_t)(row0 + r) * 128 + c];
            unsigned long long xlo = pk2(xv.x, xv.y);
            unsigned long long xhi = pk2(xv.z, xv.w);
            #pragma unroll
            for (int k = 0; k < 8; k++) {
                fma2(acc2[r][k], xlo, wlo[k]);
                fma2(acc2[r][k], xhi, whi[k]);
            }
        }
    }

    float acc[2][8];
    #pragma unroll
    for (int r = 0; r < 2; r++)
        #pragma unroll
        for (int k = 0; k < 8; k++) {
            float s = upk_sum(acc2[r][k]);
            #pragma unroll
            for (int off = 16; off > 0; off >>= 1)
                s += __shfl_xor_sync(0xFFFFFFFFu, s, off);
            acc[r][k] = s;
        }

    if (lane < 2) {
        int row = row0 + lane;
        float4 mv;
        mv.x = gelu_exact(acc[lane][0]);
        mv.y = gelu_exact(acc[lane][1]);
        mv.z = gelu_exact(acc[lane][2]);
        mv.w = gelu_exact(acc[lane][3]);
        g_m[row] = mv;
        float4 uv;
        uv.x = acc[lane][4] + sB[0];
        uv.y = acc[lane][5] + sB[1];
        uv.z = acc[lane][6] + sB[2];
        uv.w = acc[lane][7] + sB[3];
        g_u[row] = uv;
    }

    // ---- Phase B: multiplicity counts, one int2 chunk per thread ----
    int tid = blockIdx.x * 256 + t;           // [0, 1.6M) == NP/2 chunks
    int2 n2 = __ldg(&pn2[tid]);
    int2 e2 = __ldg(&pe2[tid]);
    int erep = (t & (NREP - 1)) * NE;
    atomicAdd(&g_s.ecnt[erep + e2.x], 1.0f);
    atomicAdd(&g_s.ncnt[n2.x], 1.0f);
    atomicAdd(&g_s.ecnt[erep + e2.y], 1.0f);
    atomicAdd(&g_s.ncnt[n2.y], 1.0f);
}

// ---------------- kernel 2: pair scatter #1 (node msgs -> edge sums) ----------------
// PDL: index loads (pure inputs) run BEFORE the grid dependency sync, so this
// kernel's DRAM prologue overlaps k_linear's L2/compute tail.
__global__ __launch_bounds__(256) void k_scatter_edges(
    const int4* __restrict__ pn4,
    const int4* __restrict__ pe4)
{
    int t = blockIdx.x * blockDim.x + threadIdx.x;
    int4 n4 = __ldg(&pn4[t]);
    int4 e4 = __ldg(&pe4[t]);
    int erep = (threadIdx.x & (NREP - 1)) * NE;

    cudaGridDependencySynchronize();          // wait: g_m ready

    #pragma unroll
    for (int j = 0; j < 4; j++) {
        int n = (j == 0) ? n4.x : (j == 1) ? n4.y : (j == 2) ? n4.z : n4.w;
        int e = (j == 0) ? e4.x : (j == 1) ? e4.y : (j == 2) ? e4.z : e4.w;
        float4 mv = g_m[n];
        atomicAdd(&g_s.esum[erep + e], mv);      // RED.128 (only atomic here)
    }
}

// ---------------- kernel 3: edge mean (sum replicas) ----------------
__global__ void k_edge_mean() {
    cudaGridDependencySynchronize();          // launch-latency hiding only
    int e = blockIdx.x * blockDim.x + threadIdx.x;
    if (e >= NE) return;
    float4 s = make_float4(0.f, 0.f, 0.f, 0.f);
    float cnt = 0.0f;
    #pragma unroll
    for (int r = 0; r < NREP; r++) {
        float4 v = g_s.esum[r * NE + e];
        s.x += v.x; s.y += v.y; s.z += v.z; s.w += v.w;
        cnt += g_s.ecnt[r * NE + e];
    }
    float inv = 1.0f / fmaxf(cnt, 1.0f);
    g_ef[e] = make_float4(s.x * inv, s.y * inv, s.z * inv, s.w * inv);
}

// ---------------- kernel 4: pair scatter #2 (edge means -> node sums) ----------------
__global__ __launch_bounds__(256) void k_scatter_nodes(
    const int4* __restrict__ pn4,
    const int4* __restrict__ pe4)
{
    int t = blockIdx.x * blockDim.x + threadIdx.x;
    int4 n4 = __ldg(&pn4[t]);
    int4 e4 = __ldg(&pe4[t]);

    cudaGridDependencySynchronize();          // wait: g_ef ready

    #pragma unroll
    for (int j = 0; j < 4; j++) {
        int n = (j == 0) ? n4.x : (j == 1) ? n4.y : (j == 2) ? n4.z : n4.w;
        int e = (j == 0) ? e4.x : (j == 1) ? e4.y : (j == 2) ? e4.z : e4.w;
        float4 ev = g_ef[e];
        atomicAdd(&g_s.nsum[n], ev);             // RED.128 (only atomic here)
    }
}

// ---------------- kernel 5: update + log_softmax ----------------
__global__ void k_final(float4* __restrict__ out4) {
    cudaGridDependencySynchronize();          // launch-latency hiding only
    int i = blockIdx.x * blockDim.x + threadIdx.x;
    if (i >= NN) return;
    float4 u = g_u[i];
    float4 s = g_s.nsum[i];
    float inv = 1.0f / fmaxf(g_s.ncnt[i], 1.0f);
    float h0 = gelu_exact(u.x + s.x * inv);
    float h1 = gelu_exact(u.y + s.y * inv);
    float h2 = gelu_exact(u.z + s.z * inv);
    float h3 = gelu_exact(u.w + s.w * inv);
    float mx = fmaxf(fmaxf(h0, h1), fmaxf(h2, h3));
    float lse = mx + logf(expf(h0 - mx) + expf(h1 - mx)
                        + expf(h2 - mx) + expf(h3 - mx));
    out4[i] = make_float4(h0 - lse, h1 - lse, h2 - lse, h3 - lse);
}

// ---------------- PDL launch helper ----------------
template <typename K, typename... Args>
static void launch_pdl(K kernel, dim3 grid, dim3 block, Args... args) {
    cudaLaunchConfig_t cfg = {};
    cfg.gridDim = grid;
    cfg.blockDim = block;
    cfg.dynamicSmemBytes = 0;
    cfg.stream = 0;
    cudaLaunchAttribute attr[1];
    attr[0].id = cudaLaunchAttributeProgrammaticStreamSerialization;
    attr[0].val.programmaticStreamSerializationAllowed = 1;
    cfg.attrs = attr;
    cfg.numAttrs = 1;
    cudaLaunchKernelEx(&cfg, kernel, args...);
}

// ---------------- launch ----------------
extern "C" void kernel_launch(void* const* d_in, const int* in_sizes, int n_in,
                              void* d_out, int out_size) {
    const float* x         = (const float*)d_in[0];
    const int*   pair_node = (const int*)d_in[1];
    const int*   pair_edge = (const int*)d_in[2];
    const float* W_msg     = (const float*)d_in[3];
    const float* W_upd     = (const float*)d_in[4];
    const float* b_upd     = (const float*)d_in[5];
    float4* out4 = (float4*)d_out;

    static void* scratch_ptr = nullptr;
    if (!scratch_ptr) cudaGetSymbolAddress(&scratch_ptr, g_s);
    cudaMemsetAsync(scratch_ptr, 0, sizeof(Scratch));

    k_linear<<<NN / 16, 256>>>((const float4*)x,
                               (const float4*)W_msg,
                               (const float4*)W_upd,
                               b_upd,
                               (const int2*)pair_node,
                               (const int2*)pair_edge);

    launch_pdl(k_scatter_edges, dim3(NP / 4 / 256), dim3(256),
               (const int4*)pair_node, (const int4*)pair_edge);

    launch_pdl(k_edge_mean, dim3((NE + 255) / 256), dim3(256));

    launch_pdl(k_scatter_nodes, dim3(NP / 4 / 256), dim3(256),
               (const int4*)pair_node, (const int4*)pair_edge);

    launch_pdl(k_final, dim3((NN + 255) / 256), dim3(256), out4);
}